// round 2
// baseline (speedup 1.0000x reference)
#include <cuda_runtime.h>
#include <math.h>

// Problem constants (B=4, N=8192, C=512, H=8, D=64)
#define BATCH 4
#define SEQ   8192
#define DIM   512
#define HEADS 8
#define HDIM  64
#define BH    (BATCH*HEADS)            // 32
#define MROWS (BATCH*SEQ)              // 32768
#define SCALE 0.125f                   // 64^-0.5

// Scratch (allocation-free: __device__ globals)
__device__ float g_phiq[BH*SEQ*HDIM];      // 64 MB
__device__ float g_phik[BH*SEQ*HDIM];      // 64 MB
__device__ float g_v   [BH*SEQ*HDIM];      // 64 MB
__device__ float g_attn[MROWS*DIM];        // 64 MB
__device__ float g_kvpart[32*BH*HDIM*HDIM];// 16 MB  (32 N-splits)
__device__ float g_kv  [BH*HDIM*HDIM];     // 512 KB

__device__ __forceinline__ float phi_f(float x) {
    // elu(x)+1 : x>0 -> x+1 ; else exp(x)
    return (x > 0.0f) ? (x + 1.0f) : expf(x);
}

// ---------------------------------------------------------------------------
// Tiled SGEMM: C[M,N] = A[M,K] @ B[N,K]^T  (both K-contiguous row-major)
// BM=BN=128, BK=16, 256 threads, 8x8 per thread.
// MODE 0: QKV epilogue -> scatter phi(q),phi(k),v into [BH,N,D] buffers
// MODE 1: proj epilogue -> +bias, write C row-major (A is g_attn)
// ---------------------------------------------------------------------------
template<int MODE>
__global__ void __launch_bounds__(256)
sgemm_kernel(const float* __restrict__ A, const float* __restrict__ Bm,
             const float* __restrict__ bias, float* __restrict__ Cout,
             int M, int N, int K)
{
    __shared__ float As[16][132];
    __shared__ float Bs[16][132];

    const int tid = threadIdx.x;
    const int tx = tid & 15;       // 0..15 -> col block of 8
    const int ty = tid >> 4;       // 0..15 -> row block of 8

    const int rowBase = blockIdx.y * 128;
    const int colBase = blockIdx.x * 128;

    const float* Ap = (MODE == 1) ? g_attn : A;

    const int loadRow = tid >> 2;         // 0..63
    const int loadCol = (tid & 3) * 4;    // 0,4,8,12

    const float* Aptr = Ap + (size_t)(rowBase + loadRow) * K + loadCol;
    const float* Bptr = Bm + (size_t)(colBase + loadRow) * K + loadCol;

    float acc[8][8];
    #pragma unroll
    for (int i = 0; i < 8; i++)
        #pragma unroll
        for (int j = 0; j < 8; j++) acc[i][j] = 0.0f;

    const int nkt = K >> 4;
    for (int kt = 0; kt < nkt; kt++) {
        float4 a0 = *(const float4*)(Aptr + kt * 16);
        float4 a1 = *(const float4*)(Aptr + (size_t)64 * K + kt * 16);
        float4 b0 = *(const float4*)(Bptr + kt * 16);
        float4 b1 = *(const float4*)(Bptr + (size_t)64 * K + kt * 16);

        __syncthreads();
        As[loadCol+0][loadRow] = a0.x; As[loadCol+1][loadRow] = a0.y;
        As[loadCol+2][loadRow] = a0.z; As[loadCol+3][loadRow] = a0.w;
        As[loadCol+0][loadRow+64] = a1.x; As[loadCol+1][loadRow+64] = a1.y;
        As[loadCol+2][loadRow+64] = a1.z; As[loadCol+3][loadRow+64] = a1.w;
        Bs[loadCol+0][loadRow] = b0.x; Bs[loadCol+1][loadRow] = b0.y;
        Bs[loadCol+2][loadRow] = b0.z; Bs[loadCol+3][loadRow] = b0.w;
        Bs[loadCol+0][loadRow+64] = b1.x; Bs[loadCol+1][loadRow+64] = b1.y;
        Bs[loadCol+2][loadRow+64] = b1.z; Bs[loadCol+3][loadRow+64] = b1.w;
        __syncthreads();

        #pragma unroll
        for (int k = 0; k < 16; k++) {
            float4 av0 = *(const float4*)&As[k][ty * 8];
            float4 av1 = *(const float4*)&As[k][ty * 8 + 4];
            float4 bv0 = *(const float4*)&Bs[k][tx * 8];
            float4 bv1 = *(const float4*)&Bs[k][tx * 8 + 4];
            float a[8] = {av0.x, av0.y, av0.z, av0.w, av1.x, av1.y, av1.z, av1.w};
            float b[8] = {bv0.x, bv0.y, bv0.z, bv0.w, bv1.x, bv1.y, bv1.z, bv1.w};
            #pragma unroll
            for (int i = 0; i < 8; i++)
                #pragma unroll
                for (int j = 0; j < 8; j++)
                    acc[i][j] = fmaf(a[i], b[j], acc[i][j]);
        }
    }

    if (MODE == 0) {
        // scatter q/k (with phi) and v into [BH, SEQ, HDIM]
        #pragma unroll
        for (int i = 0; i < 8; i++) {
            int gr = rowBase + ty * 8 + i;
            int b  = gr >> 13;          // /8192
            int n  = gr & 8191;
            #pragma unroll
            for (int jg = 0; jg < 8; jg += 4) {
                int gc = colBase + tx * 8 + jg;
                int which = gc >> 9;          // 0=q,1=k,2=v
                int h = (gc >> 6) & 7;
                int d = gc & 63;
                float4 v4 = make_float4(acc[i][jg], acc[i][jg+1], acc[i][jg+2], acc[i][jg+3]);
                float* dst;
                if (which == 0) {
                    v4.x = phi_f(v4.x); v4.y = phi_f(v4.y);
                    v4.z = phi_f(v4.z); v4.w = phi_f(v4.w);
                    dst = g_phiq;
                } else if (which == 1) {
                    v4.x = phi_f(v4.x); v4.y = phi_f(v4.y);
                    v4.z = phi_f(v4.z); v4.w = phi_f(v4.w);
                    dst = g_phik;
                } else {
                    dst = g_v;
                }
                size_t idx = ((size_t)((b * 8 + h) * SEQ + n) << 6) + d;
                *(float4*)&dst[idx] = v4;
            }
        }
    } else {
        #pragma unroll
        for (int i = 0; i < 8; i++) {
            int gr = rowBase + ty * 8 + i;
            #pragma unroll
            for (int jg = 0; jg < 8; jg += 4) {
                int gc = colBase + tx * 8 + jg;
                float4 bb = *(const float4*)&bias[gc];
                float4 v4 = make_float4(acc[i][jg]   + bb.x, acc[i][jg+1] + bb.y,
                                        acc[i][jg+2] + bb.z, acc[i][jg+3] + bb.w);
                *(float4*)&Cout[(size_t)gr * N + gc] = v4;
            }
        }
    }
}

// ---------------------------------------------------------------------------
// kv partials: for (bh, split s): partial[s][bh][d][e] = sum_{n in split} phik[n,d]*v[n,e]
// 32 splits of 256 rows. 256 threads, 4x4 per thread.
// ---------------------------------------------------------------------------
__global__ void __launch_bounds__(256)
kv_partial_kernel()
{
    const int bh = blockIdx.x;   // 0..31
    const int s  = blockIdx.y;   // 0..31
    const float* pk = g_phik + (size_t)bh * SEQ * HDIM;
    const float* pv = g_v    + (size_t)bh * SEQ * HDIM;
    const int n0 = s * 256;

    __shared__ float sk[16][64];
    __shared__ float sv[16][64];

    const int tid = threadIdx.x;
    const int tx = tid & 15;     // e block of 4
    const int ty = tid >> 4;     // d block of 4
    const int lr  = tid >> 4;    // load row 0..15
    const int lc4 = (tid & 15) * 4;

    float acc[4][4];
    #pragma unroll
    for (int i = 0; i < 4; i++)
        #pragma unroll
        for (int j = 0; j < 4; j++) acc[i][j] = 0.0f;

    for (int base = 0; base < 256; base += 16) {
        __syncthreads();
        *(float4*)&sk[lr][lc4] = *(const float4*)&pk[(size_t)(n0 + base + lr) * 64 + lc4];
        *(float4*)&sv[lr][lc4] = *(const float4*)&pv[(size_t)(n0 + base + lr) * 64 + lc4];
        __syncthreads();
        #pragma unroll
        for (int r = 0; r < 16; r++) {
            float4 kd = *(const float4*)&sk[r][ty * 4];
            float4 ve = *(const float4*)&sv[r][tx * 4];
            float kda[4] = {kd.x, kd.y, kd.z, kd.w};
            float vea[4] = {ve.x, ve.y, ve.z, ve.w};
            #pragma unroll
            for (int i = 0; i < 4; i++)
                #pragma unroll
                for (int j = 0; j < 4; j++)
                    acc[i][j] = fmaf(kda[i], vea[j], acc[i][j]);
        }
    }

    float* out = g_kvpart + ((size_t)(s * 32 + bh)) * 4096;
    #pragma unroll
    for (int i = 0; i < 4; i++) {
        float4 v4 = make_float4(acc[i][0], acc[i][1], acc[i][2], acc[i][3]);
        *(float4*)&out[(ty * 4 + i) * 64 + tx * 4] = v4;
    }
}

__global__ void kv_reduce_kernel()
{
    int idx = blockIdx.x * blockDim.x + threadIdx.x;  // 0..131071
    float sacc = 0.0f;
    #pragma unroll
    for (int p = 0; p < 32; p++) sacc += g_kvpart[(size_t)p * 131072 + idx];
    g_kv[idx] = sacc * SCALE;
}

// ---------------------------------------------------------------------------
// attn = phi(q) @ kv  -> g_attn[b*SEQ+n][h*64+e]
// block: (bh, tile of 64 rows). 256 threads, 4x4 per thread.
// skv: stride 64 (row-wise float4 reads only -> aligned, broadcast).
// sq : stride 65 (column-wise SCALAR reads only -> no bank conflicts,
//      and no vector access so the odd stride is alignment-safe).
// ---------------------------------------------------------------------------
__global__ void __launch_bounds__(256)
attn_apply_kernel()
{
    const int bh   = blockIdx.x;       // 0..31
    const int n0   = blockIdx.y * 64;  // 128 tiles
    const int b    = bh >> 3;
    const int h    = bh & 7;

    __shared__ float skv[64][64];
    __shared__ float sq [64][65];

    const int tid = threadIdx.x;
    const int tx = tid & 15;     // e block of 4
    const int ty = tid >> 4;     // row block of 4

    const float* kvp = g_kv + (size_t)bh * 4096;
    const float* qp  = g_phiq + (size_t)bh * SEQ * HDIM;

    for (int t = tid; t < 4096; t += 256) {
        skv[t >> 6][t & 63] = kvp[t];
        sq [t >> 6][t & 63] = qp[(size_t)(n0 + (t >> 6)) * 64 + (t & 63)];
    }
    __syncthreads();

    float acc[4][4];
    #pragma unroll
    for (int i = 0; i < 4; i++)
        #pragma unroll
        for (int j = 0; j < 4; j++) acc[i][j] = 0.0f;

    #pragma unroll 8
    for (int d = 0; d < 64; d++) {
        float4 ke = *(const float4*)&skv[d][tx * 4];
        float kea[4] = {ke.x, ke.y, ke.z, ke.w};
        float qa[4];
        #pragma unroll
        for (int i = 0; i < 4; i++) qa[i] = sq[ty * 4 + i][d];
        #pragma unroll
        for (int i = 0; i < 4; i++)
            #pragma unroll
            for (int j = 0; j < 4; j++)
                acc[i][j] = fmaf(qa[i], kea[j], acc[i][j]);
    }

    #pragma unroll
    for (int i = 0; i < 4; i++) {
        int n = n0 + ty * 4 + i;
        float4 v4 = make_float4(acc[i][0], acc[i][1], acc[i][2], acc[i][3]);
        *(float4*)&g_attn[(size_t)(b * SEQ + n) * DIM + h * 64 + tx * 4] = v4;
    }
}

// ---------------------------------------------------------------------------
extern "C" void kernel_launch(void* const* d_in, const int* in_sizes, int n_in,
                              void* d_out, int out_size)
{
    const float* x      = (const float*)d_in[0];
    const float* w_qkv  = (const float*)d_in[1];
    const float* w_proj = (const float*)d_in[2];
    const float* b_proj = (const float*)d_in[3];
    float* out = (float*)d_out;

    dim3 blk(256);

    // 1) QKV GEMM + phi + scatter
    sgemm_kernel<0><<<dim3(3 * DIM / 128, MROWS / 128), blk>>>(
        x, w_qkv, nullptr, nullptr, MROWS, 3 * DIM, DIM);

    // 2) kv partials over 32 N-splits
    kv_partial_kernel<<<dim3(32, 32), blk>>>();

    // 3) reduce partials (+ scale)
    kv_reduce_kernel<<<512, 256>>>();

    // 4) phi(q) @ kv -> g_attn
    attn_apply_kernel<<<dim3(32, 128), blk>>>();

    // 5) proj GEMM + bias -> out
    sgemm_kernel<1><<<dim3(DIM / 128, MROWS / 128), blk>>>(
        nullptr, w_proj, b_proj, out, MROWS, DIM, DIM);
}

// round 10
// speedup vs baseline: 1.0590x; 1.0590x over previous
#include <cuda_runtime.h>
#include <math.h>
#include <cstdint>

// Problem constants (B=4, N=8192, C=512, H=8, D=64)
#define BATCH 4
#define SEQ   8192
#define DIM   512
#define HEADS 8
#define HDIM  64
#define BH    (BATCH*HEADS)            // 32
#define MROWS (BATCH*SEQ)              // 32768
#define SCALE 0.125f                   // 64^-0.5

// Scratch (allocation-free: __device__ globals)
__device__ float g_phiq[BH*SEQ*HDIM];      // 64 MB
__device__ float g_phik[BH*SEQ*HDIM];      // 64 MB
__device__ float g_v   [BH*SEQ*HDIM];      // 64 MB
__device__ float g_attn[MROWS*DIM];        // 64 MB
__device__ float g_kvpart[32*BH*HDIM*HDIM];// 16 MB  (32 N-splits)
__device__ float g_kv  [BH*HDIM*HDIM];     // 512 KB

typedef unsigned long long ull;

// ---- packed f32x2 FMA (PTX ISA 8.6, plain sm_100 — NOT an 'a' feature) ----
__device__ __forceinline__ void ffma2(ull& c, ull a, ull b) {
    asm("fma.rn.f32x2 %0, %1, %2, %0;" : "+l"(c) : "l"(a), "l"(b));
}
__device__ __forceinline__ ull bcast2(float a) {
    ull r; asm("mov.b64 %0, {%1, %1};" : "=l"(r) : "f"(a)); return r;
}

__device__ __forceinline__ float phi_f(float x) {
    return (x > 0.0f) ? (x + 1.0f) : expf(x);   // elu(x)+1
}

// ---------------------------------------------------------------------------
// Tiled SGEMM: C[M,N] = A[M,K] @ B[N,K]^T  (both K-contiguous row-major)
// BM=BN=128, BK=16, 256 threads, 8x8 per thread — identical structure to the
// PASSING R2 kernel; only the inner product uses packed fma.rn.f32x2
// (acc pairs in 64-bit regs; B pairs loaded directly as ulonglong2).
// MODE 0: QKV epilogue -> phi + scatter. MODE 1: proj epilogue -> +bias.
// ---------------------------------------------------------------------------
template<int MODE>
__global__ void __launch_bounds__(256)
sgemm_kernel(const float* __restrict__ A, const float* __restrict__ Bm,
             const float* __restrict__ bias, float* __restrict__ Cout,
             int M, int N, int K)
{
    __shared__ float As[16][132];
    __shared__ float Bs[16][132];

    const int tid = threadIdx.x;
    const int tx = tid & 15;       // col block of 8
    const int ty = tid >> 4;       // row block of 8

    const int rowBase = blockIdx.y * 128;
    const int colBase = blockIdx.x * 128;

    const float* Ap = (MODE == 1) ? g_attn : A;

    const int loadRow = tid >> 2;         // 0..63
    const int loadCol = (tid & 3) * 4;    // 0,4,8,12

    const float* Aptr = Ap + (size_t)(rowBase + loadRow) * K + loadCol;
    const float* Bptr = Bm + (size_t)(colBase + loadRow) * K + loadCol;

    ull acc2[8][4];                 // 8 rows x 4 column-pairs, packed f32x2
    #pragma unroll
    for (int i = 0; i < 8; i++)
        #pragma unroll
        for (int j = 0; j < 4; j++) acc2[i][j] = 0ULL;   // {0.f,0.f}

    const int nkt = K >> 4;
    for (int kt = 0; kt < nkt; kt++) {
        float4 a0 = *(const float4*)(Aptr + kt * 16);
        float4 a1 = *(const float4*)(Aptr + (size_t)64 * K + kt * 16);
        float4 b0 = *(const float4*)(Bptr + kt * 16);
        float4 b1 = *(const float4*)(Bptr + (size_t)64 * K + kt * 16);

        __syncthreads();
        As[loadCol+0][loadRow] = a0.x; As[loadCol+1][loadRow] = a0.y;
        As[loadCol+2][loadRow] = a0.z; As[loadCol+3][loadRow] = a0.w;
        As[loadCol+0][loadRow+64] = a1.x; As[loadCol+1][loadRow+64] = a1.y;
        As[loadCol+2][loadRow+64] = a1.z; As[loadCol+3][loadRow+64] = a1.w;
        Bs[loadCol+0][loadRow] = b0.x; Bs[loadCol+1][loadRow] = b0.y;
        Bs[loadCol+2][loadRow] = b0.z; Bs[loadCol+3][loadRow] = b0.w;
        Bs[loadCol+0][loadRow+64] = b1.x; Bs[loadCol+1][loadRow+64] = b1.y;
        Bs[loadCol+2][loadRow+64] = b1.z; Bs[loadCol+3][loadRow+64] = b1.w;
        __syncthreads();

        #pragma unroll
        for (int k = 0; k < 16; k++) {
            // A: 8 scalars (broadcast into packed pairs)
            float4 av0 = *(const float4*)&As[k][ty * 8];
            float4 av1 = *(const float4*)&As[k][ty * 8 + 4];
            // B: 4 packed pairs, loaded directly as 64-bit values.
            // offsets: (k*132 + tx*8)*4 B -> k*528 + tx*32, both %16==0 ✓
            ulonglong2 bp0 = *(const ulonglong2*)&Bs[k][tx * 8];
            ulonglong2 bp1 = *(const ulonglong2*)&Bs[k][tx * 8 + 4];
            float a[8] = {av0.x, av0.y, av0.z, av0.w, av1.x, av1.y, av1.z, av1.w};
            #pragma unroll
            for (int i = 0; i < 8; i++) {
                ull pa = bcast2(a[i]);
                ffma2(acc2[i][0], pa, bp0.x);
                ffma2(acc2[i][1], pa, bp0.y);
                ffma2(acc2[i][2], pa, bp1.x);
                ffma2(acc2[i][3], pa, bp1.y);
            }
        }
    }

    if (MODE == 0) {
        // scatter q/k (with phi) and v into [BH, SEQ, HDIM]
        #pragma unroll
        for (int i = 0; i < 8; i++) {
            int gr = rowBase + ty * 8 + i;
            int b  = gr >> 13;          // /8192
            int n  = gr & 8191;
            #pragma unroll
            for (int jp = 0; jp < 4; jp += 2) {     // two float4 groups
                int gc = colBase + tx * 8 + jp * 2;
                int which = gc >> 9;          // 0=q,1=k,2=v
                int h = (gc >> 6) & 7;
                int d = gc & 63;
                float2 p0 = *(float2*)&acc2[i][jp];
                float2 p1 = *(float2*)&acc2[i][jp + 1];
                float4 v4 = make_float4(p0.x, p0.y, p1.x, p1.y);
                float* dst;
                if (which == 0) {
                    v4.x = phi_f(v4.x); v4.y = phi_f(v4.y);
                    v4.z = phi_f(v4.z); v4.w = phi_f(v4.w);
                    dst = g_phiq;
                } else if (which == 1) {
                    v4.x = phi_f(v4.x); v4.y = phi_f(v4.y);
                    v4.z = phi_f(v4.z); v4.w = phi_f(v4.w);
                    dst = g_phik;
                } else {
                    dst = g_v;
                }
                size_t idx = ((size_t)((b * 8 + h) * SEQ + n) << 6) + d;
                *(float4*)&dst[idx] = v4;
            }
        }
    } else {
        #pragma unroll
        for (int i = 0; i < 8; i++) {
            int gr = rowBase + ty * 8 + i;
            #pragma unroll
            for (int jp = 0; jp < 4; jp += 2) {
                int gc = colBase + tx * 8 + jp * 2;
                float4 bb = *(const float4*)&bias[gc];
                float2 p0 = *(float2*)&acc2[i][jp];
                float2 p1 = *(float2*)&acc2[i][jp + 1];
                float4 v4 = make_float4(p0.x + bb.x, p0.y + bb.y,
                                        p1.x + bb.z, p1.y + bb.w);
                *(float4*)&Cout[(size_t)gr * N + gc] = v4;
            }
        }
    }
}

// ---------------------------------------------------------------------------
// kv partials: partial[s][bh][d][e] = sum_{n in split s} phik[n,d]*v[n,e]
// (unchanged from the passing R2 kernel)
// ---------------------------------------------------------------------------
__global__ void __launch_bounds__(256)
kv_partial_kernel()
{
    const int bh = blockIdx.x;   // 0..31
    const int s  = blockIdx.y;   // 0..31
    const float* pk = g_phik + (size_t)bh * SEQ * HDIM;
    const float* pv = g_v    + (size_t)bh * SEQ * HDIM;
    const int n0 = s * 256;

    __shared__ float sk[16][64];
    __shared__ float sv[16][64];

    const int tid = threadIdx.x;
    const int tx = tid & 15;     // e block of 4
    const int ty = tid >> 4;     // d block of 4
    const int lr  = tid >> 4;
    const int lc4 = (tid & 15) * 4;

    float acc[4][4];
    #pragma unroll
    for (int i = 0; i < 4; i++)
        #pragma unroll
        for (int j = 0; j < 4; j++) acc[i][j] = 0.0f;

    for (int base = 0; base < 256; base += 16) {
        __syncthreads();
        *(float4*)&sk[lr][lc4] = *(const float4*)&pk[(size_t)(n0 + base + lr) * 64 + lc4];
        *(float4*)&sv[lr][lc4] = *(const float4*)&pv[(size_t)(n0 + base + lr) * 64 + lc4];
        __syncthreads();
        #pragma unroll
        for (int r = 0; r < 16; r++) {
            float4 kd = *(const float4*)&sk[r][ty * 4];
            float4 ve = *(const float4*)&sv[r][tx * 4];
            float kda[4] = {kd.x, kd.y, kd.z, kd.w};
            float vea[4] = {ve.x, ve.y, ve.z, ve.w};
            #pragma unroll
            for (int i = 0; i < 4; i++)
                #pragma unroll
                for (int j = 0; j < 4; j++)
                    acc[i][j] = fmaf(kda[i], vea[j], acc[i][j]);
        }
    }

    float* out = g_kvpart + ((size_t)(s * 32 + bh)) * 4096;
    #pragma unroll
    for (int i = 0; i < 4; i++) {
        float4 v4 = make_float4(acc[i][0], acc[i][1], acc[i][2], acc[i][3]);
        *(float4*)&out[(ty * 4 + i) * 64 + tx * 4] = v4;
    }
}

__global__ void kv_reduce_kernel()
{
    int idx = blockIdx.x * blockDim.x + threadIdx.x;  // 0..131071
    float sacc = 0.0f;
    #pragma unroll
    for (int p = 0; p < 32; p++) sacc += g_kvpart[(size_t)p * 131072 + idx];
    g_kv[idx] = sacc * SCALE;
}

// ---------------------------------------------------------------------------
// attn = phi(q) @ kv  -> g_attn[b*SEQ+n][h*64+e]
// (unchanged from the passing R2 kernel: skv stride 64, sq stride 65)
// ---------------------------------------------------------------------------
__global__ void __launch_bounds__(256)
attn_apply_kernel()
{
    const int bh   = blockIdx.x;       // 0..31
    const int n0   = blockIdx.y * 64;  // 128 tiles
    const int b    = bh >> 3;
    const int h    = bh & 7;

    __shared__ float skv[64][64];
    __shared__ float sq [64][65];

    const int tid = threadIdx.x;
    const int tx = tid & 15;     // e block of 4
    const int ty = tid >> 4;     // row block of 4

    const float* kvp = g_kv + (size_t)bh * 4096;
    const float* qp  = g_phiq + (size_t)bh * SEQ * HDIM;

    for (int t = tid; t < 4096; t += 256) {
        skv[t >> 6][t & 63] = kvp[t];
        sq [t >> 6][t & 63] = qp[(size_t)(n0 + (t >> 6)) * 64 + (t & 63)];
    }
    __syncthreads();

    float acc[4][4];
    #pragma unroll
    for (int i = 0; i < 4; i++)
        #pragma unroll
        for (int j = 0; j < 4; j++) acc[i][j] = 0.0f;

    #pragma unroll 8
    for (int d = 0; d < 64; d++) {
        float4 ke = *(const float4*)&skv[d][tx * 4];
        float kea[4] = {ke.x, ke.y, ke.z, ke.w};
        float qa[4];
        #pragma unroll
        for (int i = 0; i < 4; i++) qa[i] = sq[ty * 4 + i][d];
        #pragma unroll
        for (int i = 0; i < 4; i++)
            #pragma unroll
            for (int j = 0; j < 4; j++)
                acc[i][j] = fmaf(qa[i], kea[j], acc[i][j]);
    }

    #pragma unroll
    for (int i = 0; i < 4; i++) {
        int n = n0 + ty * 4 + i;
        float4 v4 = make_float4(acc[i][0], acc[i][1], acc[i][2], acc[i][3]);
        *(float4*)&g_attn[(size_t)(b * SEQ + n) * DIM + h * 64 + tx * 4] = v4;
    }
}

// ---------------------------------------------------------------------------
extern "C" void kernel_launch(void* const* d_in, const int* in_sizes, int n_in,
                              void* d_out, int out_size)
{
    const float* x      = (const float*)d_in[0];
    const float* w_qkv  = (const float*)d_in[1];
    const float* w_proj = (const float*)d_in[2];
    const float* b_proj = (const float*)d_in[3];
    float* out = (float*)d_out;

    dim3 blk(256);

    // 1) QKV GEMM (f32x2 packed) + phi + scatter
    sgemm_kernel<0><<<dim3(3 * DIM / 128, MROWS / 128), blk>>>(
        x, w_qkv, nullptr, nullptr, MROWS, 3 * DIM, DIM);

    // 2) kv partials over 32 N-splits
    kv_partial_kernel<<<dim3(32, 32), blk>>>();

    // 3) reduce partials (+ scale)
    kv_reduce_kernel<<<512, 256>>>();

    // 4) phi(q) @ kv -> g_attn
    attn_apply_kernel<<<dim3(32, 128), blk>>>();

    // 5) proj GEMM (f32x2 packed) + bias -> out
    sgemm_kernel<1><<<dim3(DIM / 128, MROWS / 128), blk>>>(
        nullptr, w_proj, b_proj, out, MROWS, DIM, DIM);
}